// round 4
// baseline (speedup 1.0000x reference)
#include <cuda_runtime.h>

#define T_DIM  128
#define C_IN   16
#define H_DIM  64
#define W_DIM  64
#define C_OUT  64

// Scratch for conv output [T, C_OUT, H, W] = 134 MB (device global: allowed scratch)
__device__ float g_conv[(size_t)T_DIM * C_OUT * H_DIM * W_DIM];

// Packed f32x2 FMA (full-rate fp32 path on sm_103a; ptxas never auto-emits FFMA2)
#define FMA2(acc, xp, wp) \
    asm("fma.rn.f32x2 %0, %1, %2, %0;" : "+l"(acc) : "l"(xp), "l"(wp))

// smem layout: Ws2[144][64] float2 (weights duplicated into both f32x2 lanes) = 73728 B
//              xs [16][4][68] floats (4 rows incl. halo, 1-float left shift + pad) = 17408 B
#define SMEM_W_F2   (144 * 64)           // float2 elements
#define SMEM_BYTES  (SMEM_W_F2 * 8 + 16 * 4 * 68 * 4)

// Block: 256 threads = 8 warps. Warp wg owns c_out [8*wg, 8*wg+8).
// All warps share the same 2 output rows (2*ry, 2*ry+1). Lane: lanes 0-15 row0,
// 16-31 row1; each lane computes 4 consecutive cols (2 f32x2 pixel pairs).
// Grid: blockIdx.x = t*32 + ry  (4096 blocks)
__global__ void __launch_bounds__(256)
conv3x3_kernel(const float* __restrict__ x,
               const float* __restrict__ Wt,
               const float* __restrict__ bias)
{
    extern __shared__ float smem[];
    float2* Ws2 = (float2*)smem;
    float*  xs  = smem + SMEM_W_F2 * 2;

    const int tid = threadIdx.x;
    const int t   = blockIdx.x >> 5;
    const int ry  = blockIdx.x & 31;

    // ---- load weights, transpose [c][ci*9+r] -> [r][c], duplicate into float2 ----
#pragma unroll
    for (int k = 0; k < 36; k++) {
        int i = tid + k * 256;            // 9216 weights
        float w = Wt[i];                  // coalesced
        int c = i / 144;
        int r = i - c * 144;              // r = ci*9 + kh*3 + kw (OIHW inner order)
        Ws2[r * 64 + c] = make_float2(w, w);
    }

    // ---- load x tile: rows 2*ry-1 .. 2*ry+2, all 16 ci, shifted by +1 with zero pads ----
#pragma unroll
    for (int k = 0; k < 16; k++) {
        int i  = tid + k * 256;           // 4096 elems
        int w  = i & 63;
        int rt = (i >> 6) & 3;
        int ci = i >> 8;
        int grow = 2 * ry + rt - 1;
        float v = 0.f;
        if (grow >= 0 && grow < H_DIM)
            v = x[(((size_t)t * C_IN + ci) * H_DIM + grow) * W_DIM + w];
        xs[(ci * 4 + rt) * 68 + 1 + w] = v;
    }
    if (tid < 64) {                        // zero the halo pads of all 64 tile rows
        xs[tid * 68 + 0]  = 0.f;
        xs[tid * 68 + 65] = 0.f;
        xs[tid * 68 + 66] = 0.f;
        xs[tid * 68 + 67] = 0.f;
    }
    __syncthreads();

    const int wg   = tid >> 5;            // c_out group (uniform per warp)
    const int lane = tid & 31;
    const int rl   = lane >> 4;           // row within pair
    const int c4   = lane & 15;           // col group: pixels 4*c4 .. 4*c4+3
    const int c0   = wg * 8;

    // acc[j][p] : c_out c0+j, pixel pair p (pixels 4c4+2p, 4c4+2p+1), init = bias
    unsigned long long acc[8][2];
#pragma unroll
    for (int j = 0; j < 8; j++) {
        float bv = bias[c0 + j];
        unsigned long long p;
        asm("mov.b64 %0, {%1, %2};" : "=l"(p) : "f"(bv), "f"(bv));
        acc[j][0] = p; acc[j][1] = p;
    }

#pragma unroll 1
    for (int ci = 0; ci < C_IN; ci++) {
#pragma unroll
        for (int kh = 0; kh < 3; kh++) {
            // xr[0..5] = x[4c4-1 .. 4c4+4] for input row (2ry + rl + kh - 1)
            const float* xr = xs + (ci * 4 + rl + kh) * 68 + (c4 << 2);
            float4 q  = *(const float4*)xr;        // LDS.128, 16B aligned
            float2 q2 = *(const float2*)(xr + 4);  // LDS.64
            unsigned long long p01, p12, p23, p34, p45;
            asm("mov.b64 %0,{%1,%2};" : "=l"(p01) : "f"(q.x),  "f"(q.y));
            asm("mov.b64 %0,{%1,%2};" : "=l"(p12) : "f"(q.y),  "f"(q.z));
            asm("mov.b64 %0,{%1,%2};" : "=l"(p23) : "f"(q.z),  "f"(q.w));
            asm("mov.b64 %0,{%1,%2};" : "=l"(p34) : "f"(q.w),  "f"(q2.x));
            asm("mov.b64 %0,{%1,%2};" : "=l"(p45) : "f"(q2.x), "f"(q2.y));
            unsigned long long pr0[3] = {p01, p12, p23};   // pair0 per kw
            unsigned long long pr1[3] = {p23, p34, p45};   // pair1 per kw

            // warp-uniform (broadcast) duplicated-weight loads
            const ulonglong2* wq =
                (const ulonglong2*)(Ws2 + ((ci * 9 + kh * 3) * 64 + c0));
#pragma unroll
            for (int kw = 0; kw < 3; kw++) {
                const ulonglong2* w4 = wq + kw * 32;       // kw stride: 64 float2
                ulonglong2 a = w4[0], b = w4[1], c = w4[2], d = w4[3];
                unsigned long long wv[8] = {a.x, a.y, b.x, b.y, c.x, c.y, d.x, d.y};
#pragma unroll
                for (int j = 0; j < 8; j++) {
                    FMA2(acc[j][0], pr0[kw], wv[j]);
                    FMA2(acc[j][1], pr1[kw], wv[j]);
                }
            }
        }
    }

    // ---- epilogue: unpack and store 8 float4 rows ----
    const int row = 2 * ry + rl;
    float* op = g_conv + (((size_t)t * C_OUT + c0) * H_DIM + row) * W_DIM + (c4 << 2);
#pragma unroll
    for (int j = 0; j < 8; j++) {
        float x0, x1, x2, x3;
        asm("mov.b64 {%0,%1}, %2;" : "=f"(x0), "=f"(x1) : "l"(acc[j][0]));
        asm("mov.b64 {%0,%1}, %2;" : "=f"(x2), "=f"(x3) : "l"(acc[j][1]));
        *(float4*)(op + (size_t)j * H_DIM * W_DIM) = make_float4(x0, x1, x2, x3);
    }
}

// LIF scan over T per (c,h,w): state += conv; spike = state>=8 -> reset 0;
// else state = max(state, -1). Thread handles 4 consecutive w (float4).
__global__ void __launch_bounds__(256)
lif_scan_kernel(float* __restrict__ out)
{
    const int idx = blockIdx.x * 256 + threadIdx.x;       // 0..65535
    const float4* cv = (const float4*)g_conv;
    float4* ov = (float4*)out;
    float4 s = make_float4(0.f, 0.f, 0.f, 0.f);
#pragma unroll 4
    for (int t = 0; t < T_DIM; t++) {
        float4 c = cv[(size_t)t * 65536 + idx];
        s.x += c.x; s.y += c.y; s.z += c.z; s.w += c.w;
        float4 sp;
        sp.x = (s.x >= 8.f) ? 1.f : 0.f;
        sp.y = (s.y >= 8.f) ? 1.f : 0.f;
        sp.z = (s.z >= 8.f) ? 1.f : 0.f;
        sp.w = (s.w >= 8.f) ? 1.f : 0.f;
        s.x = (s.x >= 8.f) ? 0.f : fmaxf(s.x, -1.f);
        s.y = (s.y >= 8.f) ? 0.f : fmaxf(s.y, -1.f);
        s.z = (s.z >= 8.f) ? 0.f : fmaxf(s.z, -1.f);
        s.w = (s.w >= 8.f) ? 0.f : fmaxf(s.w, -1.f);
        ov[(size_t)t * 65536 + idx] = sp;
    }
}

extern "C" void kernel_launch(void* const* d_in, const int* in_sizes, int n_in,
                              void* d_out, int out_size)
{
    const float* x  = (const float*)d_in[0];   // [128,16,64,64]
    const float* Wt = (const float*)d_in[1];   // [64,16,3,3]
    const float* b  = (const float*)d_in[2];   // [64]
    float* out = (float*)d_out;                // [128,64,64,64]

    cudaFuncSetAttribute(conv3x3_kernel,
                         cudaFuncAttributeMaxDynamicSharedMemorySize, SMEM_BYTES);

    conv3x3_kernel<<<T_DIM * 32, 256, SMEM_BYTES>>>(x, Wt, b);
    lif_scan_kernel<<<256, 256>>>(out);
}

// round 5
// speedup vs baseline: 1.9794x; 1.9794x over previous
#include <cuda_runtime.h>

#define T_DIM  128
#define C_IN   16
#define H_DIM  64
#define W_DIM  64
#define C_OUT  64
#define TPB    4            // timesteps per conv block

// Conv scratch [T+1, C_OUT, H, W]; +1 pad slice so the scan can prefetch t+1
// unconditionally. ~135 MB device-global scratch (allowed).
__device__ float g_conv[(size_t)(T_DIM + 1) * C_OUT * H_DIM * W_DIM];
// Pre-transposed, lane-duplicated weights: [r=ci*9+kh*3+kw][c_out] float2
__device__ float2 g_wpack[144 * 64];

// Packed f32x2 FMA (full-rate fp32 on sm_103a; ptxas never auto-emits FFMA2)
#define FMA2(acc, xp, wp) \
    asm("fma.rn.f32x2 %0, %1, %2, %0;" : "+l"(acc) : "l"(xp), "l"(wp))

#define SMEM_W_F2   (144 * 64)                       // float2 elements
#define SMEM_BYTES  (SMEM_W_F2 * 8 + 16 * 4 * 68 * 4)  // 91136 B

// One-time weight transpose+duplicate: OIHW -> [r][c] float2{w,w}
__global__ void wpack_kernel(const float* __restrict__ Wt)
{
    int i = blockIdx.x * 256 + threadIdx.x;          // 0..9215
    float w = Wt[i];
    int c = i / 144;
    int r = i - c * 144;
    g_wpack[r * 64 + c] = make_float2(w, w);
}

// Block: 256 thr = 8 warps. Warp wg owns c_out [8wg, 8wg+8). Lanes 0-15 row 2ry,
// 16-31 row 2ry+1; each lane computes 4 consecutive cols (2 f32x2 pairs).
// Block processes TPB consecutive timesteps (weights loaded once).
// Grid per launch: 512 = 16 t-groups x 32 row-pairs; t = t0 + tg*TPB + tt.
__global__ void __launch_bounds__(256, 2)
conv3x3_kernel(const float* __restrict__ x,
               const float* __restrict__ bias,
               int t0)
{
    extern __shared__ float smem[];
    float2* Ws2 = (float2*)smem;
    float*  xs  = smem + SMEM_W_F2 * 2;

    const int tid = threadIdx.x;
    const int tg  = blockIdx.x >> 5;
    const int ry  = blockIdx.x & 31;

    // ---- weights: conflict-free linear float4 copy from prepacked global ----
    {
        const float4* wp  = (const float4*)g_wpack;
        float4*       wsm = (float4*)smem;
#pragma unroll
        for (int k = 0; k < 18; k++)
            wsm[tid + k * 256] = wp[tid + k * 256];
    }
    // halo pads (cols 0,65,66,67 of each of 64 tile rows) — zero once
    if (tid < 64) {
        xs[tid * 68 + 0]  = 0.f;
        xs[tid * 68 + 65] = 0.f;
        xs[tid * 68 + 66] = 0.f;
        xs[tid * 68 + 67] = 0.f;
    }

    const int wg   = tid >> 5;
    const int lane = tid & 31;
    const int rl   = lane >> 4;
    const int c4   = lane & 15;
    const int c0   = wg * 8;

    float bv[8];
#pragma unroll
    for (int j = 0; j < 8; j++) bv[j] = bias[c0 + j];

    for (int tt = 0; tt < TPB; tt++) {
        const int t = t0 + tg * TPB + tt;

        // ---- x tile: rows 2ry-1..2ry+2, all 16 ci, +1 col shift, coalesced ----
#pragma unroll
        for (int k = 0; k < 16; k++) {
            int i  = tid + k * 256;
            int w  = i & 63;
            int rt = (i >> 6) & 3;
            int ci = i >> 8;
            int grow = 2 * ry + rt - 1;
            float v = 0.f;
            if (grow >= 0 && grow < H_DIM)
                v = x[(((size_t)t * C_IN + ci) * H_DIM + grow) * W_DIM + w];
            xs[(ci * 4 + rt) * 68 + 1 + w] = v;
        }
        __syncthreads();

        unsigned long long acc[8][2];
#pragma unroll
        for (int j = 0; j < 8; j++) {
            unsigned long long p;
            asm("mov.b64 %0, {%1, %2};" : "=l"(p) : "f"(bv[j]), "f"(bv[j]));
            acc[j][0] = p; acc[j][1] = p;
        }

#pragma unroll 1
        for (int ci = 0; ci < C_IN; ci++) {
#pragma unroll
            for (int kh = 0; kh < 3; kh++) {
                const float* xr = xs + (ci * 4 + rl + kh) * 68 + (c4 << 2);
                float4 q  = *(const float4*)xr;        // LDS.128 (16B aligned)
                float2 q2 = *(const float2*)(xr + 4);  // LDS.64
                unsigned long long p01, p12, p23, p34, p45;
                asm("mov.b64 %0,{%1,%2};" : "=l"(p01) : "f"(q.x),  "f"(q.y));
                asm("mov.b64 %0,{%1,%2};" : "=l"(p12) : "f"(q.y),  "f"(q.z));
                asm("mov.b64 %0,{%1,%2};" : "=l"(p23) : "f"(q.z),  "f"(q.w));
                asm("mov.b64 %0,{%1,%2};" : "=l"(p34) : "f"(q.w),  "f"(q2.x));
                asm("mov.b64 %0,{%1,%2};" : "=l"(p45) : "f"(q2.x), "f"(q2.y));
                unsigned long long pr0[3] = {p01, p12, p23};
                unsigned long long pr1[3] = {p23, p34, p45};

                const ulonglong2* wq =
                    (const ulonglong2*)(Ws2 + ((ci * 9 + kh * 3) * 64 + c0));
#pragma unroll
                for (int kw = 0; kw < 3; kw++) {
                    const ulonglong2* w4 = wq + kw * 32;   // warp-uniform bcast
                    ulonglong2 a = w4[0], b = w4[1], c = w4[2], d = w4[3];
                    FMA2(acc[0][0], pr0[kw], a.x);  FMA2(acc[0][1], pr1[kw], a.x);
                    FMA2(acc[1][0], pr0[kw], a.y);  FMA2(acc[1][1], pr1[kw], a.y);
                    FMA2(acc[2][0], pr0[kw], b.x);  FMA2(acc[2][1], pr1[kw], b.x);
                    FMA2(acc[3][0], pr0[kw], b.y);  FMA2(acc[3][1], pr1[kw], b.y);
                    FMA2(acc[4][0], pr0[kw], c.x);  FMA2(acc[4][1], pr1[kw], c.x);
                    FMA2(acc[5][0], pr0[kw], c.y);  FMA2(acc[5][1], pr1[kw], c.y);
                    FMA2(acc[6][0], pr0[kw], d.x);  FMA2(acc[6][1], pr1[kw], d.x);
                    FMA2(acc[7][0], pr0[kw], d.y);  FMA2(acc[7][1], pr1[kw], d.y);
                }
            }
        }

        // ---- store 8 float4 rows ----
        const int row = 2 * ry + rl;
        float* op = g_conv + (((size_t)t * C_OUT + c0) * H_DIM + row) * W_DIM + (c4 << 2);
#pragma unroll
        for (int j = 0; j < 8; j++) {
            float x0, x1, x2, x3;
            asm("mov.b64 {%0,%1}, %2;" : "=f"(x0), "=f"(x1) : "l"(acc[j][0]));
            asm("mov.b64 {%0,%1}, %2;" : "=f"(x2), "=f"(x3) : "l"(acc[j][1]));
            *(float4*)(op + (size_t)j * H_DIM * W_DIM) = make_float4(x0, x1, x2, x3);
        }
        __syncthreads();   // xs readers done before next tt refill
    }
}

// LIF scan over T per element. float2 per thread, 131072 threads, 1-deep prefetch
// (pad slice t=T makes the t+1 read always in-bounds).
__global__ void __launch_bounds__(256)
lif_scan_kernel(float* __restrict__ out)
{
    const int idx = blockIdx.x * 256 + threadIdx.x;        // 0..131071
    const float2* __restrict__ cv = (const float2*)g_conv;
    float2* __restrict__ ov = (float2*)out;
    const size_t N2 = 131072;

    float2 s = make_float2(0.f, 0.f);
    float2 c = cv[idx];
#pragma unroll 4
    for (int t = 0; t < T_DIM; t++) {
        float2 cn = cv[(size_t)(t + 1) * N2 + idx];        // prefetch (pad ok)
        s.x += c.x; s.y += c.y;
        float2 sp;
        sp.x = (s.x >= 8.f) ? 1.f : 0.f;
        sp.y = (s.y >= 8.f) ? 1.f : 0.f;
        s.x = (s.x >= 8.f) ? 0.f : fmaxf(s.x, -1.f);
        s.y = (s.y >= 8.f) ? 0.f : fmaxf(s.y, -1.f);
        ov[(size_t)t * N2 + idx] = sp;
        c = cn;
    }
}

extern "C" void kernel_launch(void* const* d_in, const int* in_sizes, int n_in,
                              void* d_out, int out_size)
{
    const float* x  = (const float*)d_in[0];   // [128,16,64,64]
    const float* Wt = (const float*)d_in[1];   // [64,16,3,3]
    const float* b  = (const float*)d_in[2];   // [64]
    float* out = (float*)d_out;                // [128,64,64,64]

    cudaFuncSetAttribute(conv3x3_kernel,
                         cudaFuncAttributeMaxDynamicSharedMemorySize, SMEM_BYTES);

    wpack_kernel<<<36, 256>>>(Wt);
    conv3x3_kernel<<<512, 256, SMEM_BYTES>>>(x, b, 0);    // t 0..63
    conv3x3_kernel<<<512, 256, SMEM_BYTES>>>(x, b, 64);   // t 64..127
    lif_scan_kernel<<<512, 256>>>(out);
}

// round 6
// speedup vs baseline: 2.7998x; 1.4145x over previous
#include <cuda_runtime.h>

#define T_DIM  128
#define C_IN   16
#define H_DIM  64
#define W_DIM  64
#define C_OUT  64
#define TPB    2            // timesteps per conv block

// Conv scratch [T+2, C_OUT, H, W]; +2 pad slices so the scan can prefetch depth-2
// unconditionally. ~136 MB device-global scratch (allowed).
__device__ float g_conv[(size_t)(T_DIM + 2) * C_OUT * H_DIM * W_DIM];
// Transposed weights: [r = ci*9+kh*3+kw][c_out]  (plain float, natural c_out pairs)
__device__ float g_wpackT[144 * 64];

// Packed f32x2 FMA (full-rate fp32 on sm_103a; ptxas never auto-emits FFMA2)
#define FMA2(acc, xp, wp) \
    asm("fma.rn.f32x2 %0, %1, %2, %0;" : "+l"(acc) : "l"(xp), "l"(wp))
#define DUP2(d, v) \
    asm("mov.b64 %0, {%1, %1};" : "=l"(d) : "f"(v))

#define W_FLOATS    (144 * 64)                        // 9216 floats = 36864 B
#define XS_FLOATS   (16 * 4 * 68)                     // 4352 floats  = 17408 B
#define SMEM_BYTES  ((W_FLOATS + XS_FLOATS) * 4)      // 54272 B -> 3 blocks/SM

// One-time weight transpose: OIHW -> [r][c]
__global__ void wpack_kernel(const float* __restrict__ Wt)
{
    int i = blockIdx.x * 256 + threadIdx.x;           // 0..9215
    float w = Wt[i];                                  // coalesced read
    int c = i / 144;
    int r = i - c * 144;
    g_wpackT[r * 64 + c] = w;
}

// Block: 256 thr = 8 warps, covers 2 rows x 64 cols x 64 c_out for TPB timesteps.
// Warp wg: cg = wg>>1 owns c_out [16cg,16cg+16) as 8 float2 pairs; ch = wg&1 owns
// col half. Lane: rl = lane>>4 row-in-pair, cl = lane&15 -> pixels p0=32ch+2cl, p0+1.
// f32x2 lanes hold (c_out 2j, c_out 2j+1); x duplicated {x,x} per pair.
// Grid: blockIdx.x = tg*32 + ry, tg in [0,64), t = tg*TPB + tt.
__global__ void __launch_bounds__(256, 3)
conv3x3_kernel(const float* __restrict__ x,
               const float* __restrict__ bias)
{
    extern __shared__ float smem[];
    float* Ws = smem;                  // [144][64]
    float* xs = smem + W_FLOATS;       // [16][4][68], col i holds x[i-1]

    const int tid = threadIdx.x;
    const int tg  = blockIdx.x >> 5;
    const int ry  = blockIdx.x & 31;

    // ---- weights: conflict-free linear float4 copy from prepacked global ----
    {
        const float4* wp  = (const float4*)g_wpackT;
        float4*       wsm = (float4*)Ws;
#pragma unroll
        for (int k = 0; k < 9; k++)                    // 2304 float4
            wsm[tid + k * 256] = wp[tid + k * 256];
    }
    // halo pads (cols 0,65,66,67 of each of 64 tile rows)
    if (tid < 64) {
        xs[tid * 68 + 0]  = 0.f;
        xs[tid * 68 + 65] = 0.f;
        xs[tid * 68 + 66] = 0.f;
        xs[tid * 68 + 67] = 0.f;
    }

    const int wg   = tid >> 5;
    const int lane = tid & 31;
    const int cg   = wg >> 1;
    const int ch   = wg & 1;
    const int rl   = lane >> 4;
    const int cl   = lane & 15;
    const int p0   = ch * 32 + cl * 2;     // even pixel col
    const int c0   = cg * 16;              // c_out base (8 pairs)

    // bias pairs for the 8 c_out pairs
    unsigned long long bp[8];
#pragma unroll
    for (int j = 0; j < 8; j++) {
        float2 bb = *(const float2*)(bias + c0 + 2 * j);
        asm("mov.b64 %0, {%1, %2};" : "=l"(bp[j]) : "f"(bb.x), "f"(bb.y));
    }

    for (int tt = 0; tt < TPB; tt++) {
        const int t = tg * TPB + tt;

        // ---- x tile: rows 2ry-1..2ry+2, all 16 ci, +1 col shift, coalesced ----
#pragma unroll
        for (int k = 0; k < 16; k++) {
            int i  = tid + k * 256;
            int w  = i & 63;
            int rt = (i >> 6) & 3;
            int ci = i >> 8;
            int grow = 2 * ry + rt - 1;
            float v = 0.f;
            if (grow >= 0 && grow < H_DIM)
                v = x[(((size_t)t * C_IN + ci) * H_DIM + grow) * W_DIM + w];
            xs[(ci * 4 + rt) * 68 + 1 + w] = v;
        }
        __syncthreads();

        // acc[j][px]: c_out pair j, pixel p0+px
        unsigned long long acc[8][2];
#pragma unroll
        for (int j = 0; j < 8; j++) { acc[j][0] = bp[j]; acc[j][1] = bp[j]; }

#pragma unroll 1
        for (int ci = 0; ci < C_IN; ci++) {
#pragma unroll
            for (int kh = 0; kh < 3; kh++) {
                // x[p0-1 .. p0+2] at smem idx p0..p0+3 (p0 even -> two aligned LDS.64)
                const float* xr = xs + (ci * 4 + rl + kh) * 68 + p0;
                float2 a = *(const float2*)xr;
                float2 b = *(const float2*)(xr + 2);
                unsigned long long xd[4];
                DUP2(xd[0], a.x); DUP2(xd[1], a.y);
                DUP2(xd[2], b.x); DUP2(xd[3], b.y);

                const float* wb = Ws + (ci * 9 + kh * 3) * 64 + c0;
#pragma unroll
                for (int kw = 0; kw < 3; kw++) {
                    // 8 natural c_out pairs, warp-uniform broadcast (4x LDS.128)
                    const ulonglong2* wq = (const ulonglong2*)(wb + kw * 64);
                    ulonglong2 u0 = wq[0], u1 = wq[1], u2 = wq[2], u3 = wq[3];
                    unsigned long long xlo = xd[kw], xhi = xd[kw + 1];
                    FMA2(acc[0][0], xlo, u0.x);  FMA2(acc[0][1], xhi, u0.x);
                    FMA2(acc[1][0], xlo, u0.y);  FMA2(acc[1][1], xhi, u0.y);
                    FMA2(acc[2][0], xlo, u1.x);  FMA2(acc[2][1], xhi, u1.x);
                    FMA2(acc[3][0], xlo, u1.y);  FMA2(acc[3][1], xhi, u1.y);
                    FMA2(acc[4][0], xlo, u2.x);  FMA2(acc[4][1], xhi, u2.x);
                    FMA2(acc[5][0], xlo, u2.y);  FMA2(acc[5][1], xhi, u2.y);
                    FMA2(acc[6][0], xlo, u3.x);  FMA2(acc[6][1], xhi, u3.x);
                    FMA2(acc[7][0], xlo, u3.y);  FMA2(acc[7][1], xhi, u3.y);
                }
            }
        }

        // ---- epilogue: regroup lanes -> per-c_out float2 (px p0,p0+1) stores ----
        const int row = 2 * ry + rl;
        float* op = g_conv + (((size_t)t * C_OUT + c0) * H_DIM + row) * W_DIM + p0;
#pragma unroll
        for (int j = 0; j < 8; j++) {
            float a0, b0, a1, b1;    // aX = c_out c0+2j, bX = c0+2j+1; X = pixel
            asm("mov.b64 {%0,%1}, %2;" : "=f"(a0), "=f"(b0) : "l"(acc[j][0]));
            asm("mov.b64 {%0,%1}, %2;" : "=f"(a1), "=f"(b1) : "l"(acc[j][1]));
            *(float2*)(op + (size_t)(2 * j)     * H_DIM * W_DIM) = make_float2(a0, a1);
            *(float2*)(op + (size_t)(2 * j + 1) * H_DIM * W_DIM) = make_float2(b0, b1);
        }
        __syncthreads();   // xs readers done before next tt refill
    }
}

// LIF scan over T per element. Scalar, 262144 threads, depth-2 prefetch
// (2 pad slices make t+2 reads always in-bounds).
__global__ void __launch_bounds__(256)
lif_scan_kernel(float* __restrict__ out)
{
    const int idx = blockIdx.x * 256 + threadIdx.x;        // 0..262143
    const float* __restrict__ cv = (const float*)g_conv;
    const size_t N = 262144;

    float s  = 0.f;
    float c0 = cv[idx];
    float c1 = cv[N + idx];
#pragma unroll 4
    for (int t = 0; t < T_DIM; t++) {
        float cn = cv[(size_t)(t + 2) * N + idx];          // prefetch (pads ok)
        s += c0;
        float sp = (s >= 8.f) ? 1.f : 0.f;
        s = (s >= 8.f) ? 0.f : fmaxf(s, -1.f);
        out[(size_t)t * N + idx] = sp;
        c0 = c1; c1 = cn;
    }
}

extern "C" void kernel_launch(void* const* d_in, const int* in_sizes, int n_in,
                              void* d_out, int out_size)
{
    const float* x  = (const float*)d_in[0];   // [128,16,64,64]
    const float* Wt = (const float*)d_in[1];   // [64,16,3,3]
    const float* b  = (const float*)d_in[2];   // [64]
    float* out = (float*)d_out;                // [128,64,64,64]

    cudaFuncSetAttribute(conv3x3_kernel,
                         cudaFuncAttributeMaxDynamicSharedMemorySize, SMEM_BYTES);

    wpack_kernel<<<36, 256>>>(Wt);
    conv3x3_kernel<<<(T_DIM / TPB) * 32, 256, SMEM_BYTES>>>(x, b);  // 2048 blocks
    lif_scan_kernel<<<1024, 256>>>(out);
}